// round 14
// baseline (speedup 1.0000x reference)
#include <cuda_runtime.h>
#include <cuda_fp16.h>
#include <cstdint>

#define HDIM     128
#define NS       64
#define NRAYS    16384
#define NTHREADS 256

// ---- prep kernel smem (B tiles, ldmatrix-compatible swizzled layout) ----
#define P_BH       0
#define P_BL       34816
#define SMEM_PREP  69632
#define B_PITCH_B  272     // bytes per n-row (136 halves) -> conflict-free ldmatrix

// ---- main kernel static smem layout (bytes) ----
#define M_B3    0       // 4 floats
#define M_B2    16      // 128 floats
#define M_W3    528     // 128 x float4 = 2048
#define M_O1    2576    // 128 floats
#define M_D1    3088    // 128 floats
#define M_WT    3600    // 2 floats (warp scan totals) + pad
#define M_PART  3632    // 2 warps x 4 floats
#define M_REND  3664    // 64 rows x 5 float4 = 5120
#define M_TOTAL 8784

#define REND_S  5       // float4 units per row (4 cg + 1 pad)

// B fragment arrays: [nt(16-col block) 0..7][ks 0..7][lane 0..31] uint4 = 32KB each
__device__ uint4 g_bfh[8 * 8 * 32];
__device__ uint4 g_bfl[8 * 8 * 32];

static __device__ __forceinline__ uint32_t smem_u32(const void* p) {
    uint32_t a;
    asm("{ .reg .u64 t; cvta.to.shared.u64 t, %1; cvt.u32.u64 %0, t; }" : "=r"(a) : "l"(p));
    return a;
}

static __device__ __forceinline__ float decode_scalar(const int* p) {
    int v = *p;
    if (v >= -1000000 && v <= 1000000) return (float)v;
    return __int_as_float(v);
}

// h = relu(o + t*d) for two columns; packed fp16x2
static __device__ __forceinline__ uint32_t pack_h1(float o0, float d0, float o1v, float d1v,
                                                   float t) {
    float h0 = fmaxf(fmaf(t, d0, o0), 0.0f);
    float h1 = fmaxf(fmaf(t, d1v, o1v), 0.0f);
    __half2 hh = __floats2half2_rn(h0, h1);
    return *(uint32_t*)&hh;
}

#define MMA16816(D, A0, A1, A2, A3, B0, B1) \
    asm volatile("mma.sync.aligned.m16n8k16.row.col.f32.f16.f16.f32 " \
                 "{%0,%1,%2,%3}, {%4,%5,%6,%7}, {%8,%9}, {%0,%1,%2,%3};" \
                 : "+f"((D)[0]), "+f"((D)[1]), "+f"((D)[2]), "+f"((D)[3]) \
                 : "r"(A0), "r"(A1), "r"(A2), "r"(A3), "r"(B0), "r"(B1))

#define LDSM_X4(R0, R1, R2, R3, ADDR) \
    asm volatile("ldmatrix.sync.aligned.m8n8.x4.shared.b16 {%0,%1,%2,%3}, [%4];" \
                 : "=r"(R0), "=r"(R1), "=r"(R2), "=r"(R3) : "r"(ADDR))

// ---------------- prep: build B fragment arrays in global memory ----------------
__global__ void nerf_prep_kernel(const float* __restrict__ W2) {
    extern __shared__ char psm[];
    const uint32_t base = smem_u32(psm);
    const int tid = threadIdx.x;
    const int wid = tid >> 5;      // warp = nt block (8 warps, 8 nt blocks)
    const int lid = tid & 31;

    // fp16 split of W2^T into swizzle-pitch smem tiles (same layout as R8/R13)
    for (int i = tid; i < HDIM * HDIM; i += NTHREADS) {
        int k = i >> 7, n = i & 127;
        float w = W2[i];
        __half hh = __float2half_rn(w);
        __half hl = __float2half_rn(w - __half2float(hh));
        *(__half*)(psm + P_BH + n * B_PITCH_B + k * 2) = hh;
        *(__half*)(psm + P_BL + n * B_PITCH_B + k * 2) = hl;
    }
    __syncthreads();

    // identical ldmatrix mapping to the mainloop -> frag layout correct by construction
    const uint32_t lm_off = (uint32_t)(((lid & 7) + ((lid >> 4) & 1) * 8) * B_PITCH_B)
                          + (uint32_t)(((lid >> 3) & 1) * 16)
                          + (uint32_t)(wid * 16) * B_PITCH_B;
    const uint32_t hi = base + P_BH + lm_off;
    const uint32_t lo = base + P_BL + lm_off;

    #pragma unroll
    for (int ks = 0; ks < 8; ks++) {
        uint32_t b0, b1, b2, b3;
        LDSM_X4(b0, b1, b2, b3, hi + (uint32_t)(ks * 32));
        g_bfh[(wid * 8 + ks) * 32 + lid] = make_uint4(b0, b1, b2, b3);
        LDSM_X4(b0, b1, b2, b3, lo + (uint32_t)(ks * 32));
        g_bfl[(wid * 8 + ks) * 32 + lid] = make_uint4(b0, b1, b2, b3);
    }
}

// ---------------- main: persistent, 1 ray per CTA-iteration, 3 CTAs/SM ----------------
__global__ void __launch_bounds__(NTHREADS, 3)
nerf_fused_kernel(const float* __restrict__ origins, const float* __restrict__ dirs,
                  const float* __restrict__ W1, const float* __restrict__ b1,
                  const float* __restrict__ b2v, const float* __restrict__ W3,
                  const float* __restrict__ b3v,
                  const int* __restrict__ nearp, const int* __restrict__ farp,
                  float* __restrict__ out)
{
    __shared__ char smem[M_TOTAL];
    const int tid = threadIdx.x;
    const int wid = tid >> 5;
    const int lid = tid & 31;

    float*  b3s  = (float*)(smem + M_B3);
    float*  b2s  = (float*)(smem + M_B2);
    float*  o1s  = (float*)(smem + M_O1);
    float*  d1s  = (float*)(smem + M_D1);
    float*  wt   = (float*)(smem + M_WT);
    float*  part = (float*)(smem + M_PART);
    float4* rend = (float4*)(smem + M_REND);

    if (tid < HDIM) {
        b2s[tid] = b2v[tid];
        ((float4*)(smem + M_W3))[tid] = ((const float4*)W3)[tid];
    }
    if (tid < 4) b3s[tid] = b3v[tid];

    const float nearf = decode_scalar(nearp);
    const float farf  = decode_scalar(farp);
    const float delta = (farf - nearf) * (1.0f / (float)NS);

    // warp decomposition: rg = 32-row group (0..1), cg = 32-col group (0..3)
    const int q  = lid >> 2;           // 0..7
    const int tq = lid & 3;            // 0..3
    const int rg = wid >> 2;           // 0..1
    const int cg = wid & 3;            // 0..3
    const float tq0  = fmaf((float)(rg * 32 + q) + 0.5f, delta, nearf);
    const float dt8  = 8.0f * delta;
    const float dt16 = 16.0f * delta;

    __syncthreads();

    for (int ray = blockIdx.x; ray < NRAYS; ray += gridDim.x) {
        // ---- layer-1: o1 = o@W1 + b1, d1 = d@W1 (thread j = column, tid<128) ----
        if (tid < HDIM) {
            int j = tid;
            float w0 = W1[j], w1v = W1[HDIM + j], w2v = W1[2 * HDIM + j];
            float ox = origins[ray * 3 + 0], oy = origins[ray * 3 + 1], oz = origins[ray * 3 + 2];
            float dx = dirs[ray * 3 + 0],    dy = dirs[ray * 3 + 1],    dz = dirs[ray * 3 + 2];
            o1s[j] = fmaf(ox, w0, fmaf(oy, w1v, fmaf(oz, w2v, b1[j])));
            d1s[j] = fmaf(dx, w0, fmaf(dy, w1v, dz * w2v));
        }
        __syncthreads();

        // ---- layer-2 GEMM: warp tile m32 x n32, Ah @ (Bh + Bl), B frags from global/L1 ----
        // acc[mf*16 + ntb*8 + half*4 + i]
        float acc[32];
        #pragma unroll
        for (int i = 0; i < 32; i++) acc[i] = 0.0f;

        #pragma unroll
        for (int ks = 0; ks < 8; ks++) {
            const int c = ks * 16 + 2 * tq;
            float2 olo = *(const float2*)(o1s + c);
            float2 dlo = *(const float2*)(d1s + c);
            float2 ohi = *(const float2*)(o1s + c + 8);
            float2 dhi = *(const float2*)(d1s + c + 8);

            uint32_t a[2][4];
            #pragma unroll
            for (int mf = 0; mf < 2; mf++) {
                const float ta = fmaf((float)mf, dt16, tq0);
                const float tb = ta + dt8;
                a[mf][0] = pack_h1(olo.x, dlo.x, olo.y, dlo.y, ta);
                a[mf][1] = pack_h1(olo.x, dlo.x, olo.y, dlo.y, tb);
                a[mf][2] = pack_h1(ohi.x, dhi.x, ohi.y, dhi.y, ta);
                a[mf][3] = pack_h1(ohi.x, dhi.x, ohi.y, dhi.y, tb);
            }

            #pragma unroll
            for (int ntb = 0; ntb < 2; ntb++) {
                const int idx = (((cg * 2 + ntb) * 8 + ks) * 32) + lid;
                const uint4 bh = g_bfh[idx];
                const uint4 bl = g_bfl[idx];
                #pragma unroll
                for (int mf = 0; mf < 2; mf++) {
                    float* dA = acc + mf * 16 + ntb * 8;
                    float* dB = dA + 4;
                    MMA16816(dA, a[mf][0], a[mf][1], a[mf][2], a[mf][3], bh.x, bh.y);
                    MMA16816(dB, a[mf][0], a[mf][1], a[mf][2], a[mf][3], bh.z, bh.w);
                    MMA16816(dA, a[mf][0], a[mf][1], a[mf][2], a[mf][3], bl.x, bl.y);
                    MMA16816(dB, a[mf][0], a[mf][1], a[mf][2], a[mf][3], bl.z, bl.w);
                }
            }
        }

        // ---- epilogue: h2 = relu(D + b2); partial layer-3 over 32 cols; quad reduce ----
        #pragma unroll
        for (int mf = 0; mf < 2; mf++) {
            float pr0 = 0, pg0 = 0, pb0 = 0, ps0 = 0;
            float pr1 = 0, pg1 = 0, pb1 = 0, ps1 = 0;
            #pragma unroll
            for (int ntb = 0; ntb < 2; ntb++) {
                #pragma unroll
                for (int half = 0; half < 2; half++) {
                    const float* a4 = acc + mf * 16 + ntb * 8 + half * 4;
                    const int c0 = cg * 32 + ntb * 16 + half * 8 + 2 * tq;
                    const float bb0 = b2s[c0], bb1 = b2s[c0 + 1];
                    const float4 wA = *(const float4*)(smem + M_W3 + c0 * 16);
                    const float4 wB = *(const float4*)(smem + M_W3 + (c0 + 1) * 16);
                    float h00 = fmaxf(a4[0] + bb0, 0.0f);
                    float h01 = fmaxf(a4[1] + bb1, 0.0f);
                    float h10 = fmaxf(a4[2] + bb0, 0.0f);
                    float h11 = fmaxf(a4[3] + bb1, 0.0f);
                    pr0 = fmaf(h00, wA.x, fmaf(h01, wB.x, pr0));
                    pg0 = fmaf(h00, wA.y, fmaf(h01, wB.y, pg0));
                    pb0 = fmaf(h00, wA.z, fmaf(h01, wB.z, pb0));
                    ps0 = fmaf(h00, wA.w, fmaf(h01, wB.w, ps0));
                    pr1 = fmaf(h10, wA.x, fmaf(h11, wB.x, pr1));
                    pg1 = fmaf(h10, wA.y, fmaf(h11, wB.y, pg1));
                    pb1 = fmaf(h10, wA.z, fmaf(h11, wB.z, pb1));
                    ps1 = fmaf(h10, wA.w, fmaf(h11, wB.w, ps1));
                }
            }
            #pragma unroll
            for (int off = 1; off <= 2; off <<= 1) {
                pr0 += __shfl_xor_sync(0xffffffffu, pr0, off);
                pg0 += __shfl_xor_sync(0xffffffffu, pg0, off);
                pb0 += __shfl_xor_sync(0xffffffffu, pb0, off);
                ps0 += __shfl_xor_sync(0xffffffffu, ps0, off);
                pr1 += __shfl_xor_sync(0xffffffffu, pr1, off);
                pg1 += __shfl_xor_sync(0xffffffffu, pg1, off);
                pb1 += __shfl_xor_sync(0xffffffffu, pb1, off);
                ps1 += __shfl_xor_sync(0xffffffffu, ps1, off);
            }
            if (tq == 0) {
                const int row = rg * 32 + mf * 16 + q;   // 0..63 (sample)
                rend[row * REND_S + cg]       = make_float4(pr0, pg0, pb0, ps0);
                rend[(row + 8) * REND_S + cg] = make_float4(pr1, pg1, pb1, ps1);
            }
        }
        __syncthreads();

        // ---- volume rendering: 64 samples, exact log-space scan (tid<64 = warps 0,1) ----
        float cr = 0, cg2 = 0, cb = 0, sd = 0, x = 0;
        if (tid < 64) {
            float4 f0 = rend[tid * REND_S + 0];
            float4 f1 = rend[tid * REND_S + 1];
            float4 f2 = rend[tid * REND_S + 2];
            float4 f3 = rend[tid * REND_S + 3];
            cr  = f0.x + f1.x + f2.x + f3.x + b3s[0];
            cg2 = f0.y + f1.y + f2.y + f3.y + b3s[1];
            cb  = f0.z + f1.z + f2.z + f3.z + b3s[2];
            sd  = (f0.w + f1.w + f2.w + f3.w + b3s[3]) * delta;

            x = sd;
            #pragma unroll
            for (int off = 1; off < 32; off <<= 1) {
                float v = __shfl_up_sync(0xffffffffu, x, off);
                if (lid >= off) x += v;
            }
            if (lid == 31) wt[wid] = x;
        }
        __syncthreads();
        if (tid < 64) {
            float pre = x - sd;
            if (wid == 1) pre += wt[0];
            float w = __expf(-pre) - __expf(-(pre + sd));

            float wr = w * cr, wg = w * cg2, wb = w * cb;
            #pragma unroll
            for (int off = 16; off > 0; off >>= 1) {
                wr += __shfl_down_sync(0xffffffffu, wr, off);
                wg += __shfl_down_sync(0xffffffffu, wg, off);
                wb += __shfl_down_sync(0xffffffffu, wb, off);
            }
            if (lid == 0) {
                float* p = part + wid * 4;
                p[0] = wr; p[1] = wg; p[2] = wb;
            }
        }
        __syncthreads();
        if (tid == 0) {
            out[ray * 3 + 0] = part[0] + part[4];
            out[ray * 3 + 1] = part[1] + part[5];
            out[ray * 3 + 2] = part[2] + part[6];
        }
        // no trailing sync: o1s/rend/wt/part are next written only after at least
        // one intervening __syncthreads in the next iteration.
    }
}

extern "C" void kernel_launch(void* const* d_in, const int* in_sizes, int n_in,
                              void* d_out, int out_size) {
    (void)in_sizes; (void)n_in; (void)out_size;
    const float* origins = (const float*)d_in[0];
    const float* dirs    = (const float*)d_in[1];
    const float* W1      = (const float*)d_in[2];
    const float* b1      = (const float*)d_in[3];
    const float* W2      = (const float*)d_in[4];
    const float* b2v     = (const float*)d_in[5];
    const float* W3      = (const float*)d_in[6];
    const float* b3v     = (const float*)d_in[7];
    const int*   nearp   = (const int*)d_in[8];
    const int*   farp    = (const int*)d_in[9];
    float* out = (float*)d_out;

    int sms = 0;
    cudaDeviceGetAttribute(&sms, cudaDevAttrMultiProcessorCount, 0);
    if (sms <= 0) sms = 148;

    cudaFuncSetAttribute(nerf_prep_kernel,
                         cudaFuncAttributeMaxDynamicSharedMemorySize, SMEM_PREP);
    nerf_prep_kernel<<<1, NTHREADS, SMEM_PREP>>>(W2);

    int grid = sms * 3;                 // persistent: 3 CTAs/SM (occupancy play)
    if (grid > NRAYS) grid = NRAYS;
    nerf_fused_kernel<<<grid, NTHREADS>>>(
        origins, dirs, W1, b1, b2v, W3, b3v, nearp, farp, out);
}